// round 7
// baseline (speedup 1.0000x reference)
#include <cuda_runtime.h>
#include <math.h>

#define N      8192
#define FIN    256
#define FOUT   64
#define NEGTH  (-1e8f)      // adj: 0.0f neighbor, -1e9 otherwise
#define ALPHA  0.2f

#define NPROJ  128          // projection blocks (bid < NPROJ)
#define NSCANB 512          // scan blocks; 8 warps x 2 rows each = 8192 rows
#define NBLK   (NPROJ + NSCANB)
#define TR     64           // rows per proj block
#define KC     32
#define NCH    (FIN / KC)
#define CAP    96           // neighbor capacity/row (E=32)

// ---------------- scratch (static __device__, allocation-free) --------------
__device__ __align__(16) static float g_fts[N * FOUT];
__device__ __align__(16) static float g_f1[N];
__device__ __align__(16) static float g_f2[N];
__device__ static int g_done;   // proj blocks finished (reset by last scan blk)
__device__ static int g_fin;    // scan blocks finished

// shared-memory overlay: proj tile vs scan lists never coexist in a block
struct ProjS {
    float xs[TR][KC + 1];
    float ws[KC * FOUT];
};
struct ScanS {
    int   idx[16][CAP];
    float wt[16][CAP];
};

__global__ __launch_bounds__(256, 5) void k_main(
        const float* __restrict__ x,   const float* __restrict__ W,
        const float* __restrict__ adj,
        const float* __restrict__ a1,  const float* __restrict__ b1,
        const float* __restrict__ a2,  const float* __restrict__ b2,
        const float* __restrict__ bias, float* __restrict__ out) {
    __shared__ __align__(16) char smem_raw[sizeof(ProjS) > sizeof(ScanS)
                                           ? sizeof(ProjS) : sizeof(ScanS)];
    const int tid  = threadIdx.x;
    const int lane = tid & 31;
    const int wid  = tid >> 5;

    if (blockIdx.x < NPROJ) {
        // ========================= projection role ==========================
        ProjS& S = *reinterpret_cast<ProjS*>(smem_raw);
        const int row0 = blockIdx.x * TR;
        const int fg = tid & 15, rg = tid >> 4;
        const int f0 = fg * 4,   r0 = rg * 4;
        const int xk = tid & 31, xr0 = tid >> 5;
        const float4* __restrict__ W4 = (const float4*)W;

        float acc[4][4] = {};
#pragma unroll
        for (int c = 0; c < NCH; c++) {
            const int kc = c * KC;
            __syncthreads();
#pragma unroll
            for (int i = 0; i < 8; i++)
                S.xs[xr0 + 8 * i][xk] = x[(size_t)(row0 + xr0 + 8 * i) * FIN + kc + xk];
            {
                float4* ws4 = (float4*)S.ws;
#pragma unroll
                for (int i = 0; i < 2; i++)
                    ws4[tid + i * 256] = W4[kc * 16 + tid + i * 256];
            }
            __syncthreads();
#pragma unroll
            for (int k = 0; k < KC; k++) {
                const float4 wv = *(const float4*)&S.ws[k * FOUT + f0];
                float xr[4];
#pragma unroll
                for (int r = 0; r < 4; r++) xr[r] = S.xs[r0 + r][k];
                const float wf[4] = {wv.x, wv.y, wv.z, wv.w};
#pragma unroll
                for (int r = 0; r < 4; r++)
#pragma unroll
                    for (int j = 0; j < 4; j++)
                        acc[r][j] = fmaf(xr[r], wf[j], acc[r][j]);
            }
        }

#pragma unroll
        for (int r = 0; r < 4; r++) {
            float4 v = make_float4(acc[r][0], acc[r][1], acc[r][2], acc[r][3]);
            *(float4*)&g_fts[(size_t)(row0 + r0 + r) * FOUT + f0] = v;
        }

        // fused f1/f2 from register accumulators
        const float4 a1v = *(const float4*)&a1[f0];
        const float4 a2v = *(const float4*)&a2[f0];
        float p1[4], p2[4];
#pragma unroll
        for (int r = 0; r < 4; r++) {
            p1[r] = acc[r][0]*a1v.x + acc[r][1]*a1v.y + acc[r][2]*a1v.z + acc[r][3]*a1v.w;
            p2[r] = acc[r][0]*a2v.x + acc[r][1]*a2v.y + acc[r][2]*a2v.z + acc[r][3]*a2v.w;
        }
#pragma unroll
        for (int o = 1; o < 16; o <<= 1) {
#pragma unroll
            for (int r = 0; r < 4; r++) {
                p1[r] += __shfl_xor_sync(0xffffffffu, p1[r], o);
                p2[r] += __shfl_xor_sync(0xffffffffu, p2[r], o);
            }
        }
        if (fg == 0) {
            const float bb1 = __ldg(b1), bb2 = __ldg(b2);
#pragma unroll
            for (int r = 0; r < 4; r++) {
                g_f1[row0 + r0 + r] = p1[r] + bb1;
                g_f2[row0 + r0 + r] = p2[r] + bb2;
            }
        }
        __threadfence();
        __syncthreads();
        if (tid == 0) atomicAdd(&g_done, 1);
        return;
    }

    // =========================== scan/finish role ===========================
    ScanS& S = *reinterpret_cast<ScanS*>(smem_raw);
    const int base = ((blockIdx.x - NPROJ) * 8 + wid) * 2;   // 2 rows per warp
    int cnt[2];

    // ---- phase A: stream both adj rows, compact neighbors (fts-free) ----
#pragma unroll
    for (int r = 0; r < 2; r++) {
        const int row  = base + r;
        const int slot = wid * 2 + r;
        const float4* __restrict__ adjr = (const float4*)(adj + (size_t)row * N);

        unsigned m[8];
#pragma unroll
        for (int w = 0; w < 8; w++) m[w] = 0;

        // 16 groups x 4 float4-loads (16 live load regs; 2 groups per mask word)
#pragma unroll
        for (int g = 0; g < 16; g++) {
            float4 av[4];
#pragma unroll
            for (int u = 0; u < 4; u++)
                av[u] = __ldcs(&adjr[(g * 4 + u) * 32 + lane]);
            unsigned nb = 0;
#pragma unroll
            for (int u = 0; u < 4; u++) {
                nb |= (av[u].x > NEGTH ? 1u : 0u) << (u * 4);
                nb |= (av[u].y > NEGTH ? 2u : 0u) << (u * 4);
                nb |= (av[u].z > NEGTH ? 4u : 0u) << (u * 4);
                nb |= (av[u].w > NEGTH ? 8u : 0u) << (u * 4);
            }
            m[g >> 1] |= nb << ((g & 1) * 16);
        }

        int lcnt = 0;
#pragma unroll
        for (int w = 0; w < 8; w++) lcnt += __popc(m[w]);

        int incl = lcnt;
#pragma unroll
        for (int o = 1; o < 32; o <<= 1) {
            int v = __shfl_up_sync(0xffffffffu, incl, o);
            if (lane >= o) incl += v;
        }
        cnt[r] = __shfl_sync(0xffffffffu, incl, 31);
        if (cnt[r] > 0 && cnt[r] <= CAP && lcnt) {
            int o = incl - lcnt;
#pragma unroll
            for (int w = 0; w < 8; w++) {
                unsigned mw = m[w];
                while (mw) {
                    const int p = __ffs(mw) - 1;
                    mw &= mw - 1;
                    S.idx[slot][o++] = (w * 8 + (p >> 2)) * 128 + lane * 4 + (p & 3);
                }
            }
        }
        __syncwarp();
    }

    // ---- wait for projection (fts, f1, f2) ----
    if (lane == 0)
        while (*(volatile int*)&g_done != NPROJ) __nanosleep(128);
    __syncwarp();
    __threadfence();

    // ---- phase B: softmax + gather per row ----
#pragma unroll
    for (int r = 0; r < 2; r++) {
        const int row   = base + r;
        const int slot  = wid * 2 + r;
        const int total = cnt[r];
        const float f1i = g_f1[row];

        if (total > 0 && total <= CAP) {
            float lm = -INFINITY;
            for (int e = lane; e < total; e += 32) {
                float s = f1i + g_f2[S.idx[slot][e]];
                s = s > 0.f ? s : ALPHA * s;
                S.wt[slot][e] = s;
                lm = fmaxf(lm, s);
            }
#pragma unroll
            for (int o = 16; o > 0; o >>= 1)
                lm = fmaxf(lm, __shfl_xor_sync(0xffffffffu, lm, o));
            float ls = 0.f;
            for (int e = lane; e < total; e += 32) {
                const float w = expf(S.wt[slot][e] - lm);
                S.wt[slot][e] = w;
                ls += w;
            }
#pragma unroll
            for (int o = 16; o > 0; o >>= 1)
                ls += __shfl_xor_sync(0xffffffffu, ls, o);
            __syncwarp();

            const float invS = 1.0f / ls;
            float acc0 = 0.f, acc1 = 0.f;
            for (int e = 0; e < total; e++) {
                const float w = S.wt[slot][e];
                const float* fr = &g_fts[(size_t)S.idx[slot][e] * FOUT];
                acc0 = fmaf(w, fr[lane],      acc0);
                acc1 = fmaf(w, fr[lane + 32], acc1);
            }
            float v0 = acc0 * invS + __ldg(&bias[lane]);
            float v1 = acc1 * invS + __ldg(&bias[lane + 32]);
            out[(size_t)row * FOUT + lane]      = v0 > 0.f ? v0 : expm1f(v0);
            out[(size_t)row * FOUT + lane + 32] = v1 > 0.f ? v1 : expm1f(v1);
        } else {
            // exact warp-scoped streaming fallback (P ~ 1e-10 per row)
            const float* __restrict__ adjs = adj + (size_t)row * N;
            float lm = -INFINITY;
            for (int j = lane; j < N; j += 32) {
                float s = f1i + g_f2[j];
                s = s > 0.f ? s : ALPHA * s;
                lm = fmaxf(lm, s + adjs[j]);
            }
#pragma unroll
            for (int o = 16; o > 0; o >>= 1)
                lm = fmaxf(lm, __shfl_xor_sync(0xffffffffu, lm, o));
            float ls = 0.f;
            for (int j = lane; j < N; j += 32) {
                float s = f1i + g_f2[j];
                s = s > 0.f ? s : ALPHA * s;
                ls += expf(s + adjs[j] - lm);
            }
#pragma unroll
            for (int o = 16; o > 0; o >>= 1)
                ls += __shfl_xor_sync(0xffffffffu, ls, o);
            const float invS = 1.0f / ls;
            float acc0 = 0.f, acc1 = 0.f;
            for (int j = 0; j < N; j++) {
                float s = f1i + g_f2[j];
                s = s > 0.f ? s : ALPHA * s;
                const float w = expf(s + adjs[j] - lm);
                if (w > 0.f) {
                    const float* fr = &g_fts[(size_t)j * FOUT];
                    acc0 = fmaf(w, fr[lane],      acc0);
                    acc1 = fmaf(w, fr[lane + 32], acc1);
                }
            }
            float v0 = acc0 * invS + __ldg(&bias[lane]);
            float v1 = acc1 * invS + __ldg(&bias[lane + 32]);
            out[(size_t)row * FOUT + lane]      = v0 > 0.f ? v0 : expm1f(v0);
            out[(size_t)row * FOUT + lane + 32] = v1 > 0.f ? v1 : expm1f(v1);
        }
    }

    // ---- self-cleaning flags for graph replay ----
    __syncthreads();
    if (tid == 0) {
        const int v = atomicAdd(&g_fin, 1);
        if (v == NSCANB - 1) {
            g_done = 0;
            g_fin  = 0;
        }
    }
}

// ---------------- launcher ---------------------------------------------------
extern "C" void kernel_launch(void* const* d_in, const int* in_sizes, int n_in,
                              void* d_out, int out_size) {
    const float* x    = (const float*)d_in[0];
    const float* adj  = (const float*)d_in[1];
    const float* W    = (const float*)d_in[2];
    const float* a1   = (const float*)d_in[3];
    const float* b1   = (const float*)d_in[4];
    const float* a2   = (const float*)d_in[5];
    const float* b2   = (const float*)d_in[6];
    const float* bias = (const float*)d_in[7];
    float* out = (float*)d_out;

    k_main<<<NBLK, 256>>>(x, W, adj, a1, b1, a2, b2, bias, out);
}